// round 8
// baseline (speedup 1.0000x reference)
#include <cuda_runtime.h>

// Problem constants
#define B_  8
#define T_  2048
#define C_  512
#define H_  64
#define BT_ (B_ * T_)
#define NTILE_ 32            // query tiles per batch (T/64)
#define NTICKETS_ (B_ * NTILE_)

// Scratch for projected q/k/v (device globals: no allocations allowed).
__device__ float g_q[BT_ * H_];
__device__ float g_k[BT_ * H_];
__device__ float g_v[BT_ * H_];
__device__ int   g_ticket;   // persistent-kernel work queue cursor

typedef unsigned long long u64;

// Packed fp32x2 helpers (Blackwell FFMA2 — only reachable via PTX).
__device__ __forceinline__ u64 pk2(float lo, float hi) {
  u64 d;
  asm("mov.b64 %0, {%1, %2};" : "=l"(d) : "f"(lo), "f"(hi));
  return d;
}
__device__ __forceinline__ void upk2(u64 d, float& lo, float& hi) {
  asm("mov.b64 {%0, %1}, %2;" : "=f"(lo), "=f"(hi) : "l"(d));
}
__device__ __forceinline__ void ffma2(u64& d, u64 a, u64 b) {
  asm("fma.rn.f32x2 %0, %1, %2, %0;" : "+l"(d) : "l"(a), "l"(b));
}

// ---------------------------------------------------------------------------
// Swizzles for 64-col tiles.
// sw : chunk ^= (row & 15)       — used by proj (unchanged from R5).
// sw4: chunk ^= ((row>>2) & 15)  — attn layout. Exact for our access set:
//   * row-major float4 stores (row=i>>4, col lanes distinct)    conflict-free
//   * stride-4-row scalar transpose stores (row=4*tx+d, col fix) conflict-free
//   * stride-4-row u64 loads   (row=4*tx+j, col=2k fixed)        conflict-free
//   * broadcast u64 loads      (row fixed per half-warp)         conflict-free
// ---------------------------------------------------------------------------
__device__ __forceinline__ int sw(int row, int col) {
  return row * 64 + ((((col >> 2) ^ (row & 15)) << 2) | (col & 3));
}
__device__ __forceinline__ int sw4(int row, int col) {
  return row * 64 + ((((col >> 2) ^ ((row >> 2) & 15)) << 2) | (col & 3));
}

// ---------------------------------------------------------------------------
// Projection (unchanged — measured at its FFMA2 floor, ~50us).
// out[r, :] = x[r, :] @ W  for W in {Wq, Wk, Wv}. Grid (256, 3), 256 thr.
// Block (0,0) resets the attention work-queue ticket each launch.
// ---------------------------------------------------------------------------
__global__ __launch_bounds__(256, 2) void proj_kernel(
    const float* __restrict__ x,
    const float* __restrict__ Wq,
    const float* __restrict__ Wk,
    const float* __restrict__ Wv) {
  __shared__ __align__(16) float xst[32 * 64];  // sw(k, row)
  __shared__ __align__(16) float ws[32][64];    // [k][col]

  if (blockIdx.x == 0 && blockIdx.y == 0 && threadIdx.x == 0)
    g_ticket = 0;  // attn_kernel launches after this grid completes

  const int which = blockIdx.y;
  const float* __restrict__ W = (which == 0) ? Wq : (which == 1 ? Wk : Wv);
  float* __restrict__ outp    = (which == 0) ? g_q : (which == 1 ? g_k : g_v);

  const int r0  = blockIdx.x * 64;
  const int tid = threadIdx.x;
  const int ty4 = (tid >> 4) << 2;
  const int tx4 = (tid & 15) << 2;

  u64 sp[2][4] = {};  // rows packed: sp[ii][j] = {s[2ii][j], s[2ii+1][j]}

  for (int kk = 0; kk < C_; kk += 32) {
    #pragma unroll
    for (int i = tid; i < 64 * 8; i += 256) {
      int r = i >> 3, c4 = (i & 7) << 2;
      float4 v = *(const float4*)&x[(size_t)(r0 + r) * C_ + kk + c4];
      xst[sw(c4 + 0, r)] = v.x;
      xst[sw(c4 + 1, r)] = v.y;
      xst[sw(c4 + 2, r)] = v.z;
      xst[sw(c4 + 3, r)] = v.w;
    }
    #pragma unroll
    for (int i = tid; i < 32 * 16; i += 256) {
      int r = i >> 4, c4 = (i & 15) << 2;
      *(float4*)&ws[r][c4] = *(const float4*)&W[(size_t)(kk + r) * H_ + c4];
    }
    __syncthreads();

    #pragma unroll 16
    for (int k = 0; k < 32; k++) {
      float4 av = *(const float4*)&xst[sw(k, ty4)];
      float4 bv = *(const float4*)&ws[k][tx4];
      u64 a0 = pk2(av.x, av.y), a1 = pk2(av.z, av.w);
      u64 b0 = pk2(bv.x, bv.x), b1 = pk2(bv.y, bv.y);
      u64 b2 = pk2(bv.z, bv.z), b3 = pk2(bv.w, bv.w);
      ffma2(sp[0][0], a0, b0); ffma2(sp[0][1], a0, b1);
      ffma2(sp[0][2], a0, b2); ffma2(sp[0][3], a0, b3);
      ffma2(sp[1][0], a1, b0); ffma2(sp[1][1], a1, b1);
      ffma2(sp[1][2], a1, b2); ffma2(sp[1][3], a1, b3);
    }
    __syncthreads();
  }

  float s[4][4];
  #pragma unroll
  for (int j = 0; j < 4; j++) {
    upk2(sp[0][j], s[0][j], s[1][j]);
    upk2(sp[1][j], s[2][j], s[3][j]);
  }
  #pragma unroll
  for (int i = 0; i < 4; i++) {
    float4 r = make_float4(s[i][0], s[i][1], s[i][2], s[i][3]);
    *(float4*)&outp[(size_t)(r0 + ty4 + i) * H_ + tx4] = r;
  }
}

// ---------------------------------------------------------------------------
// Causal attention, persistent-CTA LPT queue, unnormalized exp softmax.
// fp32x2 FFMA2 packed over the CONTRACTION dim (dot-product halves summed at
// the end) -> all operands are native u64 loads from row-major Q/K/P and
// transposed V; no pk2-duplication MOVs, no conflicted transpose of K.
// Smem: Qs (row-major sw4 Q), KP (row-major sw4 K, reused as P), Vt
// (transposed sw4 V). 48 KB static -> 2 CTAs/SM.
// ---------------------------------------------------------------------------
__global__ __launch_bounds__(256, 2) void attn_kernel(float* __restrict__ out) {
  __shared__ __align__(16) float Qs[64 * 64];  // sw4(qrow, h)
  __shared__ __align__(16) float KP[64 * 64];  // sw4(krow, h) -> sw4(qrow, kcol)
  __shared__ __align__(16) float Vt[64 * 64];  // sw4(h, krow)
  __shared__ int s_ticket;

  const int tid = threadIdx.x;
  const int ty4 = (tid >> 4) << 2;  // query-row group base (4 rows)
  const int tx4 = (tid & 15) << 2;  // key-col / head-col group base (4 cols)

  for (;;) {
    if (tid == 0) s_ticket = atomicAdd(&g_ticket, 1);
    __syncthreads();
    const int t = s_ticket;
    __syncthreads();  // all read s_ticket before tid0 can overwrite it
    if (t >= NTICKETS_) break;

    const int qt = (NTILE_ - 1) - (t >> 3);  // descending cost (LPT)
    const int b  = t & 7;
    const int q0 = qt * 64;
    const size_t base = (size_t)b * T_ * H_;
    const float* __restrict__ qp = g_q + base;
    const float* __restrict__ kp = g_k + base;
    const float* __restrict__ vp = g_v + base;

    // Q tile -> row-major sw4 (conflict-free float4 stores).
    #pragma unroll
    for (int i = tid; i < 64 * 16; i += 256) {
      int r = i >> 4, c4 = (i & 15) << 2;
      *(float4*)&Qs[sw4(r, c4)] =
          *(const float4*)&qp[(size_t)(q0 + r) * H_ + c4];
    }

    float l[4] = {0.f, 0.f, 0.f, 0.f};
    u64 opp[4][4] = {};  // o[i][h] packed over {even kk, odd kk} halves
    __syncthreads();

    for (int jt = 0; jt <= qt; jt++) {
      const int k0 = jt * 64;

      // K -> row-major sw4 KP; V -> transposed sw4 Vt (conflict-free).
      #pragma unroll
      for (int i = tid; i < 64 * 16; i += 256) {
        int r = i >> 4, c4 = (i & 15) << 2;
        *(float4*)&KP[sw4(r, c4)] =
            *(const float4*)&kp[(size_t)(k0 + r) * H_ + c4];
        float4 vv = *(const float4*)&vp[(size_t)(k0 + r) * H_ + c4];
        Vt[sw4(c4 + 0, r)] = vv.x;
        Vt[sw4(c4 + 1, r)] = vv.y;
        Vt[sw4(c4 + 2, r)] = vv.z;
        Vt[sw4(c4 + 3, r)] = vv.w;
      }
      __syncthreads();

      // S = Q @ K^T, packed over h pairs: all operands native u64 loads.
      u64 sp[4][4] = {};
      #pragma unroll 8
      for (int h2 = 0; h2 < 32; h2++) {
        u64 a[4], bb[4];
        #pragma unroll
        for (int i = 0; i < 4; i++)
          a[i] = *(const u64*)&Qs[sw4(ty4 + i, 2 * h2)];
        #pragma unroll
        for (int j = 0; j < 4; j++)
          bb[j] = *(const u64*)&KP[sw4(tx4 + j, 2 * h2)];
        #pragma unroll
        for (int i = 0; i < 4; i++)
          #pragma unroll
          for (int j = 0; j < 4; j++) ffma2(sp[i][j], a[i], bb[j]);
      }

      float s[4][4];
      #pragma unroll
      for (int i = 0; i < 4; i++)
        #pragma unroll
        for (int j = 0; j < 4; j++) {
          float lo, hi;
          upk2(sp[i][j], lo, hi);
          s[i][j] = lo + hi;
        }

      // Causal mask on the diagonal tile: kcol > qrow -> -inf (exp -> 0).
      if (jt == qt) {
        #pragma unroll
        for (int i = 0; i < 4; i++)
          #pragma unroll
          for (int j = 0; j < 4; j++)
            if (tx4 + j > ty4 + i) s[i][j] = -1e30f;
      }

      __syncthreads();  // everyone done reading KP as K

      // p = exp(s); accumulate partial l; store P row-major sw4 (float4,
      // conflict-free: chunk = tx ^ ty distinct across lanes).
      #pragma unroll
      for (int i = 0; i < 4; i++) {
        float p0 = __expf(s[i][0]), p1 = __expf(s[i][1]);
        float p2 = __expf(s[i][2]), p3 = __expf(s[i][3]);
        l[i] += (p0 + p1) + (p2 + p3);
        *(float4*)&KP[sw4(ty4 + i, tx4)] = make_float4(p0, p1, p2, p3);
      }
      __syncthreads();  // P fully written

      // O += P @ V, packed over kk pairs: p broadcast u64, v stride-4-row u64.
      #pragma unroll 8
      for (int k2 = 0; k2 < 32; k2++) {
        u64 pr[4], vr[4];
        #pragma unroll
        for (int i = 0; i < 4; i++)
          pr[i] = *(const u64*)&KP[sw4(ty4 + i, 2 * k2)];
        #pragma unroll
        for (int h = 0; h < 4; h++)
          vr[h] = *(const u64*)&Vt[sw4(tx4 + h, 2 * k2)];
        #pragma unroll
        for (int i = 0; i < 4; i++)
          #pragma unroll
          for (int h = 0; h < 4; h++) ffma2(opp[i][h], pr[i], vr[h]);
      }
      __syncthreads();  // before next tile overwrites KP/Vt
    }

    // Merge packed halves, reduce l across the 16 tx-lanes, normalize, store.
    #pragma unroll
    for (int i = 0; i < 4; i++) {
      float rs = l[i];
      #pragma unroll
      for (int d = 8; d >= 1; d >>= 1)
        rs += __shfl_xor_sync(0xffffffffu, rs, d);
      float inv = 1.0f / rs;
      float o[4];
      #pragma unroll
      for (int h = 0; h < 4; h++) {
        float lo, hi;
        upk2(opp[i][h], lo, hi);
        o[h] = (lo + hi) * inv;
      }
      *(float4*)&out[((size_t)b * T_ + q0 + ty4 + i) * H_ + tx4] =
          make_float4(o[0], o[1], o[2], o[3]);
    }
  }
}

extern "C" void kernel_launch(void* const* d_in, const int* in_sizes, int n_in,
                              void* d_out, int out_size) {
  const float* x  = (const float*)d_in[0];
  const float* Wq = (const float*)d_in[1];
  const float* Wk = (const float*)d_in[2];
  const float* Wv = (const float*)d_in[3];
  float* out = (float*)d_out;

  dim3 gp(BT_ / 64, 3);
  proj_kernel<<<gp, 256>>>(x, Wq, Wk, Wv);

  attn_kernel<<<296, 256>>>(out);
}